// round 4
// baseline (speedup 1.0000x reference)
#include <cuda_runtime.h>
#include <cstdint>
#include <math.h>

#define Bb   256
#define Ss   256
#define Tt   48
#define EMB  256
#define HID  1024
#define NLAB 128
#define G4H  (4*HID)
#define CAT3 (2*HID+EMB)   // 2304

// ---------------- scratch (device globals; no runtime allocation) ----------------
__device__ float g_ctx_proj[Bb*Ss*HID];      // [B,S,HID]   268 MB
__device__ float g_gates_x[Bb*Tt*G4H];       // [B,T,4H]    201 MB
__device__ float g_xcat[Bb*Tt*2*EMB];        // [B,T,512]    25 MB
__device__ float g_gates[Bb*G4H];
__device__ float g_hA[Bb*HID];
__device__ float g_hB[Bb*HID];
__device__ float g_cst[Bb*HID];
__device__ float g_hlstm[Bb*HID];
__device__ float g_q[Bb*HID];
__device__ float g_wtd[Bb*HID];
__device__ float g_cat2[Bb*2*HID];
__device__ float g_cat3[Bb*CAT3];

// ---------------- generic 64x64 register-tiled fp32 GEMM ----------------
// C[M,N] = A[M,K] @ B[K,N] + bias[N] (+ add[M,N] with row stride ldadd) ; act: 0=none 1=tanh
// Requires: M%64==0, N%64==0, K%16==0 (true for every call here).
__global__ void gemm64(const float* __restrict__ A, int lda,
                       const float* __restrict__ Bm, int N,
                       const float* __restrict__ bias,
                       const float* __restrict__ add, int ldadd,
                       float* __restrict__ C, int ldc,
                       int K, int act)
{
    __shared__ float As[16][64];
    __shared__ float Bs[16][64];
    const int tid  = threadIdx.x;                   // 256 threads
    const int row0 = blockIdx.y * 64;
    const int col0 = blockIdx.x * 64;
    const int tx   = tid & 15, ty = tid >> 4;
    const int arow = tid >> 2, acol = (tid & 3) * 4;
    const int brow = tid >> 4, bcol = (tid & 15) * 4;

    float acc[4][4];
    #pragma unroll
    for (int i = 0; i < 4; i++)
        #pragma unroll
        for (int j = 0; j < 4; j++) acc[i][j] = 0.f;

    const float* Ap = A  + (size_t)(row0 + arow) * lda + acol;
    const float* Bp = Bm + (size_t)brow * N + col0 + bcol;

    for (int k0 = 0; k0 < K; k0 += 16) {
        float4 av = *(const float4*)(Ap + k0);
        As[acol + 0][arow] = av.x;
        As[acol + 1][arow] = av.y;
        As[acol + 2][arow] = av.z;
        As[acol + 3][arow] = av.w;
        *(float4*)&Bs[brow][bcol] = *(const float4*)(Bp + (size_t)k0 * N);
        __syncthreads();
        #pragma unroll
        for (int k = 0; k < 16; k++) {
            float4 a = *(const float4*)&As[k][ty * 4];
            float4 b = *(const float4*)&Bs[k][tx * 4];
            float ar[4] = {a.x, a.y, a.z, a.w};
            float br[4] = {b.x, b.y, b.z, b.w};
            #pragma unroll
            for (int i = 0; i < 4; i++)
                #pragma unroll
                for (int j = 0; j < 4; j++)
                    acc[i][j] += ar[i] * br[j];
        }
        __syncthreads();
    }

    #pragma unroll
    for (int i = 0; i < 4; i++) {
        int r = row0 + ty * 4 + i;
        #pragma unroll
        for (int j = 0; j < 4; j++) {
            int c = col0 + tx * 4 + j;
            float v = acc[i][j] + bias[c];
            if (add)  v += add[(size_t)r * ldadd + c];
            if (act)  v  = tanhf(v);
            C[(size_t)r * ldc + c] = v;
        }
    }
}

// ---------------- build teacher-forced inputs: xcat = [x_seq | lab_emb] ----------------
__global__ void build_xcat(const float* __restrict__ dec, const float* __restrict__ emb,
                           const int* __restrict__ cur, const int* __restrict__ lab,
                           float* __restrict__ xcat)
{
    int idx = blockIdx.x * 256 + threadIdx.x;
    if (idx >= Bb * Tt * 2 * EMB) return;
    int j  = idx & (2 * EMB - 1);
    int bt = idx >> 9;
    int t = bt % Tt, b = bt / Tt;
    float v;
    if (j < EMB) {
        v = (t == 0) ? dec[b * EMB + j]
                     : emb[cur[b * Tt + t - 1] * EMB + j];
    } else {
        v = emb[lab[b * Tt + t] * EMB + (j - EMB)];
    }
    xcat[idx] = v;
}

// ---------------- LSTM pointwise ----------------
__global__ void lstm_pw(const float* __restrict__ gates, float* __restrict__ c,
                        float* __restrict__ hl)
{
    int idx = blockIdx.x * 256 + threadIdx.x;   // Bb*HID
    int b = idx >> 10, j = idx & 1023;
    const float* g = gates + (size_t)b * G4H;
    float ig = g[j], fg = g[HID + j], gg = g[2 * HID + j], og = g[3 * HID + j];
    float si = 1.f / (1.f + expf(-ig));
    float sf = 1.f / (1.f + expf(-fg));
    float so = 1.f / (1.f + expf(-og));
    float ct = sf * c[idx] + si * tanhf(gg);
    c[idx]  = ct;
    hl[idx] = so * tanhf(ct);
}

// ---------------- fused attention: e -> softmax -> weighted, one block per b ----------------
__global__ void attn_k(const float* __restrict__ q, const float* __restrict__ ctx,
                       const float* __restrict__ Vv, float* __restrict__ wtd)
{
    __shared__ float sQ[HID], sV[HID], sE[Ss];
    __shared__ float sred[8];
    int b = blockIdx.x;
    int tid = threadIdx.x, lane = tid & 31, warp = tid >> 5;

    for (int i = tid; i < HID; i += 256) { sQ[i] = q[b * HID + i]; sV[i] = Vv[i]; }
    __syncthreads();

    const float* cb = ctx + (size_t)b * Ss * HID;

    // phase 1: energies e[s] = sum_h V[h]*tanh(q[h]+ctx[b,s,h])   (precise tanhf, float4)
    for (int s = warp; s < Ss; s += 8) {
        const float4* row4 = (const float4*)(cb + (size_t)s * HID);
        float acc = 0.f;
        #pragma unroll
        for (int h4 = lane; h4 < HID / 4; h4 += 32) {
            float4 cv = row4[h4];
            int h = h4 * 4;
            acc += sV[h + 0] * tanhf(sQ[h + 0] + cv.x);
            acc += sV[h + 1] * tanhf(sQ[h + 1] + cv.y);
            acc += sV[h + 2] * tanhf(sQ[h + 2] + cv.z);
            acc += sV[h + 3] * tanhf(sQ[h + 3] + cv.w);
        }
        #pragma unroll
        for (int o = 16; o; o >>= 1) acc += __shfl_xor_sync(0xffffffffu, acc, o);
        if (!lane) sE[s] = acc;
    }
    __syncthreads();

    // phase 2: softmax over S=256 (one value per thread; precise expf)
    float e = sE[tid];
    float m = e;
    #pragma unroll
    for (int o = 16; o; o >>= 1) m = fmaxf(m, __shfl_xor_sync(0xffffffffu, m, o));
    if (!lane) sred[warp] = m;
    __syncthreads();
    if (warp == 0) {
        float v = sred[lane & 7];
        #pragma unroll
        for (int o = 4; o; o >>= 1) v = fmaxf(v, __shfl_xor_sync(0xffffffffu, v, o));
        if (!lane) sred[0] = v;
    }
    __syncthreads();
    float ex  = expf(e - sred[0]);
    float sum = ex;
    #pragma unroll
    for (int o = 16; o; o >>= 1) sum += __shfl_xor_sync(0xffffffffu, sum, o);
    __syncthreads();
    if (!lane) sred[warp] = sum;
    __syncthreads();
    if (warp == 0) {
        float v = sred[lane & 7];
        #pragma unroll
        for (int o = 4; o; o >>= 1) v += __shfl_xor_sync(0xffffffffu, v, o);
        if (!lane) sred[0] = v;
    }
    __syncthreads();
    sE[tid] = ex / sred[0];
    __syncthreads();

    // phase 3: weighted[b,h] = sum_s alpha[s]*ctx[b,s,h]   (float4: 4 h per thread)
    {
        int h0 = tid * 4;
        float4 acc = make_float4(0.f, 0.f, 0.f, 0.f);
        const float4* cb4 = (const float4*)(cb + h0);
        #pragma unroll 8
        for (int s = 0; s < Ss; s++) {
            float a = sE[s];
            float4 cv = cb4[(size_t)s * (HID / 4)];
            acc.x += a * cv.x;
            acc.y += a * cv.y;
            acc.z += a * cv.z;
            acc.w += a * cv.w;
        }
        *(float4*)(wtd + b * HID + h0) = acc;
    }
}

// ---------------- concat helpers ----------------
__global__ void cat2_k(const float* __restrict__ w, const float* __restrict__ hl,
                       float* __restrict__ out)
{
    int idx = blockIdx.x * 256 + threadIdx.x;   // Bb*2H
    int b = idx >> 11, j = idx & 2047;
    out[idx] = (j < HID) ? w[b * HID + j] : hl[b * HID + j - HID];
}

__global__ void cat3_k(const float* __restrict__ hid, const float* __restrict__ w,
                       const float* __restrict__ xcat, int t, float* __restrict__ out)
{
    int idx = blockIdx.x * 256 + threadIdx.x;   // Bb*2304
    if (idx >= Bb * CAT3) return;
    int b = idx / CAT3, j = idx % CAT3;
    float v;
    if      (j < HID)     v = hid[b * HID + j];
    else if (j < 2 * HID) v = w[b * HID + j - HID];
    else                  v = xcat[((size_t)b * Tt + t) * (2 * EMB) + (j - 2 * HID)];
    out[idx] = v;
}

// ---------------- argmax over NLAB (one warp per (b,t) row) ----------------
__global__ void argmax_k(const float* __restrict__ outputs, float* __restrict__ preds)
{
    int warp = (blockIdx.x * blockDim.x + threadIdx.x) >> 5;
    int lane = threadIdx.x & 31;
    if (warp >= Bb * Tt) return;
    const float* row = outputs + (size_t)warp * NLAB;
    float best = -INFINITY; int bi = 0;
    for (int j = lane; j < NLAB; j += 32) {
        float v = row[j];
        if (v > best) { best = v; bi = j; }
    }
    #pragma unroll
    for (int o = 16; o; o >>= 1) {
        float ov = __shfl_xor_sync(0xffffffffu, best, o);
        int   oi = __shfl_xor_sync(0xffffffffu, bi,   o);
        if (ov > best || (ov == best && oi < bi)) { best = ov; bi = oi; }
    }
    if (!lane) preds[warp] = (float)bi;
}

// ---------------- host ----------------
extern "C" void kernel_launch(void* const* d_in, const int* in_sizes, int n_in,
                              void* d_out, int out_size)
{
    int ix = 0;
    ix++;                                   // sent_lengths (unused)
    if (in_sizes[ix] == 1) ix++;            // output_length scalar (unused)
    const float* dec_in  = (const float*)d_in[ix++];
    const float* h0      = (const float*)d_in[ix++];
    const float* c0      = (const float*)d_in[ix++];
    const float* context = (const float*)d_in[ix++];
    const int*   cur_lab = (const int*)  d_in[ix++];
    const int*   labels  = (const int*)  d_in[ix++];
    const float* emb     = (const float*)d_in[ix++];
    const float* W_ih    = (const float*)d_in[ix++];
    const float* b_ih    = (const float*)d_in[ix++];
    const float* W_hh    = (const float*)d_in[ix++];
    const float* b_hh    = (const float*)d_in[ix++];
    const float* W_ho    = (const float*)d_in[ix++];
    const float* b_ho    = (const float*)d_in[ix++];
    const float* W_ain   = (const float*)d_in[ix++];
    const float* b_ain   = (const float*)d_in[ix++];
    const float* W_actx  = (const float*)d_in[ix++];
    const float* b_actx  = (const float*)d_in[ix++];
    const float* Vv      = (const float*)d_in[ix++];
    const float* W_out   = (const float*)d_in[ix++];
    const float* b_out   = (const float*)d_in[ix++];

    float* out     = (float*)d_out;
    float* outputs = out;                               // B*T*NLAB
    float* preds   = out + (size_t)Bb * Tt * NLAB;      // B*T
    float* hf      = preds + (size_t)Bb * Tt;           // B*HID
    float* cf      = hf + (size_t)Bb * HID;             // B*HID

    float *ctx_proj, *gates_x, *xcat, *gates, *hA, *hB, *cst, *hlstm, *qb, *wtd, *cat2, *cat3;
    cudaGetSymbolAddress((void**)&ctx_proj, g_ctx_proj);
    cudaGetSymbolAddress((void**)&gates_x,  g_gates_x);
    cudaGetSymbolAddress((void**)&xcat,     g_xcat);
    cudaGetSymbolAddress((void**)&gates,    g_gates);
    cudaGetSymbolAddress((void**)&hA,       g_hA);
    cudaGetSymbolAddress((void**)&hB,       g_hB);
    cudaGetSymbolAddress((void**)&cst,      g_cst);
    cudaGetSymbolAddress((void**)&hlstm,    g_hlstm);
    cudaGetSymbolAddress((void**)&qb,       g_q);
    cudaGetSymbolAddress((void**)&wtd,      g_wtd);
    cudaGetSymbolAddress((void**)&cat2,     g_cat2);
    cudaGetSymbolAddress((void**)&cat3,     g_cat3);

    // init recurrent state
    cudaMemcpyAsync(hA,  h0, (size_t)Bb * HID * sizeof(float), cudaMemcpyDeviceToDevice, 0);
    cudaMemcpyAsync(cst, c0, (size_t)Bb * HID * sizeof(float), cudaMemcpyDeviceToDevice, 0);

    // teacher-forced inputs
    build_xcat<<<(Bb * Tt * 2 * EMB + 255) / 256, 256>>>(dec_in, emb, cur_lab, labels, xcat);

    // gates_x = xcat @ W_ih + b_ih   [12288 x 4096], K=512
    gemm64<<<dim3(G4H / 64, (Bb * Tt) / 64), 256>>>(xcat, 2 * EMB, W_ih, G4H,
                                                    b_ih, nullptr, 0,
                                                    gates_x, G4H, 2 * EMB, 0);
    // ctx_proj = context @ W_actx + b_actx   [65536 x 1024], K=1024
    gemm64<<<dim3(HID / 64, (Bb * Ss) / 64), 256>>>(context, HID, W_actx, HID,
                                                    b_actx, nullptr, 0,
                                                    ctx_proj, HID, HID, 0);

    float* hbufs[2] = {hA, hB};
    for (int t = 0; t < Tt; t++) {
        float* hin  = hbufs[t & 1];
        float* hout = hbufs[(t + 1) & 1];

        // gates = hin @ W_hh + b_hh + gates_x[:,t,:]
        gemm64<<<dim3(G4H / 64, Bb / 64), 256>>>(hin, HID, W_hh, G4H,
                                                 b_hh, gates_x + (size_t)t * G4H, Tt * G4H,
                                                 gates, G4H, HID, 0);
        lstm_pw<<<(Bb * HID) / 256, 256>>>(gates, cst, hlstm);

        // q = hlstm @ W_ain + b_ain
        gemm64<<<dim3(HID / 64, Bb / 64), 256>>>(hlstm, HID, W_ain, HID,
                                                 b_ain, nullptr, 0,
                                                 qb, HID, HID, 0);
        // attention -> weighted
        attn_k<<<Bb, 256>>>(qb, ctx_proj, Vv, wtd);

        // hidden = tanh([weighted, hlstm] @ W_ho + b_ho)
        cat2_k<<<(Bb * 2 * HID) / 256, 256>>>(wtd, hlstm, cat2);
        gemm64<<<dim3(HID / 64, Bb / 64), 256>>>(cat2, 2 * HID, W_ho, HID,
                                                 b_ho, nullptr, 0,
                                                 hout, HID, 2 * HID, 1);

        // out[:,t,:] = [hidden, weighted, x_t] @ W_out + b_out
        cat3_k<<<(Bb * CAT3 + 255) / 256, 256>>>(hout, wtd, xcat, t, cat3);
        gemm64<<<dim3(NLAB / 64, Bb / 64), 256>>>(cat3, CAT3, W_out, NLAB,
                                                  b_out, nullptr, 0,
                                                  outputs + (size_t)t * NLAB, Tt * NLAB,
                                                  CAT3, 0);
    }

    // final states: carried hidden is post-attention hidden_t; after t=47 it sits in hbufs[0]
    cudaMemcpyAsync(hf, hbufs[Tt & 1], (size_t)Bb * HID * sizeof(float), cudaMemcpyDeviceToDevice, 0);
    cudaMemcpyAsync(cf, cst,           (size_t)Bb * HID * sizeof(float), cudaMemcpyDeviceToDevice, 0);

    // preds
    argmax_k<<<(Bb * Tt) / 8, 256>>>(outputs, preds);
}

// round 9
// speedup vs baseline: 1.3122x; 1.3122x over previous
#include <cuda_runtime.h>
#include <cstdint>
#include <math.h>

#define Bb   256
#define Ss   256
#define Tt   48
#define EMB  256
#define HID  1024
#define NLAB 128
#define G4H  (4*HID)
#define CAT3 (2*HID+EMB)   // 2304

// ---------------- scratch (device globals; no runtime allocation) ----------------
__device__ float g_ctx_proj[Bb*Ss*HID];      // [B,S,HID] raw projected context   268 MB
__device__ float g_tp[Bb*Ss*HID];            // tanh(ctx_proj)                    268 MB
__device__ float g_gates_x[Bb*Tt*G4H];       // [B,T,4H]                          201 MB
__device__ float g_xcat[Bb*Tt*2*EMB];        // [B,T,512]                          25 MB
__device__ float g_cat3all[(size_t)Bb*Tt*CAT3]; // [B*T, 2304] rows for W_out     113 MB
__device__ float g_gates[Bb*G4H];
__device__ float g_hA[Bb*HID];
__device__ float g_hB[Bb*HID];
__device__ float g_cst[Bb*HID];
__device__ float g_hlstm[Bb*HID];
__device__ float g_q[Bb*HID];                // holds tq = tanh(q)

// ---------------- generic 64x64 register-tiled fp32 GEMM ----------------
// C[M,N] = concatK(A, A2) @ B[K,N] + bias[N] (+ add) ; act: 0=none 1=tanh
// A covers k in [0,K1), A2 covers k in [K1,K) (A2 may be null -> single source; K1 must be %16==0).
// Optional dup-store to C2. Requires M%64==0, N%64==0, K%16==0.
__global__ void gemm64(const float* __restrict__ A, int lda,
                       const float* __restrict__ A2, int lda2, int K1,
                       const float* __restrict__ Bm, int N,
                       const float* __restrict__ bias,
                       const float* __restrict__ add, int ldadd,
                       float* __restrict__ C, int ldc,
                       float* __restrict__ C2, int ldc2,
                       int K, int act)
{
    __shared__ float As[16][64];
    __shared__ float Bs[16][64];
    const int tid  = threadIdx.x;                   // 256 threads
    const int row0 = blockIdx.y * 64;
    const int col0 = blockIdx.x * 64;
    const int tx   = tid & 15, ty = tid >> 4;
    const int arow = tid >> 2, acol = (tid & 3) * 4;
    const int brow = tid >> 4, bcol = (tid & 15) * 4;

    float acc[4][4];
    #pragma unroll
    for (int i = 0; i < 4; i++)
        #pragma unroll
        for (int j = 0; j < 4; j++) acc[i][j] = 0.f;

    const float* Bp = Bm + (size_t)brow * N + col0 + bcol;

    for (int k0 = 0; k0 < K; k0 += 16) {
        int kk = k0 + acol;
        const float* src;
        if (A2 && kk >= K1) src = A2 + (size_t)(row0 + arow) * lda2 + (kk - K1);
        else                src = A  + (size_t)(row0 + arow) * lda  + kk;
        float4 av = *(const float4*)src;
        As[acol + 0][arow] = av.x;
        As[acol + 1][arow] = av.y;
        As[acol + 2][arow] = av.z;
        As[acol + 3][arow] = av.w;
        *(float4*)&Bs[brow][bcol] = *(const float4*)(Bp + (size_t)k0 * N);
        __syncthreads();
        #pragma unroll
        for (int k = 0; k < 16; k++) {
            float4 a = *(const float4*)&As[k][ty * 4];
            float4 b = *(const float4*)&Bs[k][tx * 4];
            float ar[4] = {a.x, a.y, a.z, a.w};
            float br[4] = {b.x, b.y, b.z, b.w};
            #pragma unroll
            for (int i = 0; i < 4; i++)
                #pragma unroll
                for (int j = 0; j < 4; j++)
                    acc[i][j] += ar[i] * br[j];
        }
        __syncthreads();
    }

    #pragma unroll
    for (int i = 0; i < 4; i++) {
        int r = row0 + ty * 4 + i;
        #pragma unroll
        for (int j = 0; j < 4; j++) {
            int c = col0 + tx * 4 + j;
            float v = acc[i][j] + bias[c];
            if (add)  v += add[(size_t)r * ldadd + c];
            if (act)  v  = tanhf(v);
            C[(size_t)r * ldc + c] = v;
            if (C2) C2[(size_t)r * ldc2 + c] = v;
        }
    }
}

// ---------------- build teacher-forced inputs: xcat = [x_seq | lab_emb] ----------------
__global__ void build_xcat(const float* __restrict__ dec, const float* __restrict__ emb,
                           const int* __restrict__ cur, const int* __restrict__ lab,
                           float* __restrict__ xcat)
{
    int idx = blockIdx.x * 256 + threadIdx.x;
    if (idx >= Bb * Tt * 2 * EMB) return;
    int j  = idx & (2 * EMB - 1);
    int bt = idx >> 9;
    int t = bt % Tt, b = bt / Tt;
    float v;
    if (j < EMB) {
        v = (t == 0) ? dec[b * EMB + j]
                     : emb[cur[b * Tt + t - 1] * EMB + j];
    } else {
        v = emb[lab[b * Tt + t] * EMB + (j - EMB)];
    }
    xcat[idx] = v;
}

// ---------------- elementwise tanh (precompute TP = tanh(ctx_proj)) ----------------
__global__ void tanh_ew(const float* __restrict__ in, float* __restrict__ out, int n)
{
    int idx = blockIdx.x * 256 + threadIdx.x;
    if (idx < n) out[idx] = tanhf(in[idx]);
}

// ---------------- copy x part of xcat into cat3all[..., 2H:2H+EMB] (once) ----------------
__global__ void xcat_to_cat3(const float* __restrict__ xcat, float* __restrict__ cat3all)
{
    int idx = blockIdx.x * 256 + threadIdx.x;   // Bb*Tt*EMB
    if (idx >= Bb * Tt * EMB) return;
    int j = idx & (EMB - 1);
    int m = idx >> 8;                            // b*Tt + t
    cat3all[(size_t)m * CAT3 + 2 * HID + j] = xcat[(size_t)m * (2 * EMB) + j];
}

// ---------------- LSTM pointwise ----------------
__global__ void lstm_pw(const float* __restrict__ gates, float* __restrict__ c,
                        float* __restrict__ hl)
{
    int idx = blockIdx.x * 256 + threadIdx.x;   // Bb*HID
    int b = idx >> 10, j = idx & 1023;
    const float* g = gates + (size_t)b * G4H;
    float ig = g[j], fg = g[HID + j], gg = g[2 * HID + j], og = g[3 * HID + j];
    float si = 1.f / (1.f + expf(-ig));
    float sf = 1.f / (1.f + expf(-fg));
    float so = 1.f / (1.f + expf(-og));
    float ct = sf * c[idx] + si * tanhf(gg);
    c[idx]  = ct;
    hl[idx] = so * tanhf(ct);
}

// ---------------- fused attention (tanh addition identity) ----------------
// energies: e[s] = sum_h V[h] * (tq[h]+TP[s,h]) / (1 + tq[h]*TP[s,h])
// then softmax, then weighted[b,h] = sum_s alpha[s]*ctx_proj[b,s,h] -> cat3all slot.
// 512 threads per block, one block per b.
__global__ void attn_k(const float* __restrict__ tq, const float* __restrict__ tp,
                       const float* __restrict__ ctx, const float* __restrict__ Vv,
                       float* __restrict__ cat3all, int t)
{
    __shared__ float sQ[HID], sV[HID], sE[Ss];
    __shared__ float sred[16];
    int b = blockIdx.x;
    int tid = threadIdx.x, lane = tid & 31, warp = tid >> 5;   // 16 warps

    for (int i = tid; i < HID; i += 512) { sQ[i] = tq[b * HID + i]; sV[i] = Vv[i]; }
    __syncthreads();

    const float* tb = tp + (size_t)b * Ss * HID;

    // phase 1: energies via addition identity (exact algebra, cheap ops)
    for (int s = warp; s < Ss; s += 16) {
        const float4* row4 = (const float4*)(tb + (size_t)s * HID);
        float acc = 0.f;
        #pragma unroll
        for (int h4 = lane; h4 < HID / 4; h4 += 32) {
            float4 tpv = row4[h4];
            int h = h4 * 4;
            acc += sV[h + 0] * __fdividef(sQ[h + 0] + tpv.x, fmaf(sQ[h + 0], tpv.x, 1.f));
            acc += sV[h + 1] * __fdividef(sQ[h + 1] + tpv.y, fmaf(sQ[h + 1], tpv.y, 1.f));
            acc += sV[h + 2] * __fdividef(sQ[h + 2] + tpv.z, fmaf(sQ[h + 2], tpv.z, 1.f));
            acc += sV[h + 3] * __fdividef(sQ[h + 3] + tpv.w, fmaf(sQ[h + 3], tpv.w, 1.f));
        }
        #pragma unroll
        for (int o = 16; o; o >>= 1) acc += __shfl_xor_sync(0xffffffffu, acc, o);
        if (!lane) sE[s] = acc;
    }
    __syncthreads();

    // phase 2: softmax over S=256 (threads 0..255 own one value; all 512 hit syncs)
    float e = (tid < Ss) ? sE[tid] : -INFINITY;
    float m = e;
    #pragma unroll
    for (int o = 16; o; o >>= 1) m = fmaxf(m, __shfl_xor_sync(0xffffffffu, m, o));
    if (!lane) sred[warp] = m;                    // warps 8..15 write -inf
    __syncthreads();
    if (warp == 0) {
        float v = (lane < 16) ? sred[lane] : -INFINITY;
        #pragma unroll
        for (int o = 8; o; o >>= 1) v = fmaxf(v, __shfl_xor_sync(0xffffffffu, v, o));
        if (!lane) sred[0] = v;
    }
    __syncthreads();
    float mx = sred[0];
    __syncthreads();
    float ex  = (tid < Ss) ? expf(e - mx) : 0.f;
    float sum = ex;
    #pragma unroll
    for (int o = 16; o; o >>= 1) sum += __shfl_xor_sync(0xffffffffu, sum, o);
    if (!lane) sred[warp] = sum;
    __syncthreads();
    if (warp == 0) {
        float v = (lane < 16) ? sred[lane] : 0.f;
        #pragma unroll
        for (int o = 8; o; o >>= 1) v += __shfl_xor_sync(0xffffffffu, v, o);
        if (!lane) sred[0] = v;
    }
    __syncthreads();
    if (tid < Ss) sE[tid] = ex / sred[0];
    __syncthreads();

    // phase 3: weighted over raw ctx_proj; write straight into cat3all wtd slot
    {
        int h0 = tid * 2;                          // 512 threads x 2 h
        const float2* cb2 = (const float2*)(ctx + (size_t)b * Ss * HID + h0);
        float2 acc = make_float2(0.f, 0.f);
        #pragma unroll 8
        for (int s = 0; s < Ss; s++) {
            float a = sE[s];
            float2 cv = cb2[(size_t)s * (HID / 2)];
            acc.x += a * cv.x;
            acc.y += a * cv.y;
        }
        *(float2*)(cat3all + ((size_t)b * Tt + t) * CAT3 + HID + h0) = acc;
    }
}

// ---------------- argmax over NLAB (one warp per (b,t) row) ----------------
__global__ void argmax_k(const float* __restrict__ outputs, float* __restrict__ preds)
{
    int warp = (blockIdx.x * blockDim.x + threadIdx.x) >> 5;
    int lane = threadIdx.x & 31;
    if (warp >= Bb * Tt) return;
    const float* row = outputs + (size_t)warp * NLAB;
    float best = -INFINITY; int bi = 0;
    for (int j = lane; j < NLAB; j += 32) {
        float v = row[j];
        if (v > best) { best = v; bi = j; }
    }
    #pragma unroll
    for (int o = 16; o; o >>= 1) {
        float ov = __shfl_xor_sync(0xffffffffu, best, o);
        int   oi = __shfl_xor_sync(0xffffffffu, bi,   o);
        if (ov > best || (ov == best && oi < bi)) { best = ov; bi = oi; }
    }
    if (!lane) preds[warp] = (float)bi;
}

// ---------------- host ----------------
extern "C" void kernel_launch(void* const* d_in, const int* in_sizes, int n_in,
                              void* d_out, int out_size)
{
    int ix = 0;
    ix++;                                   // sent_lengths (unused)
    if (in_sizes[ix] == 1) ix++;            // output_length scalar (unused)
    const float* dec_in  = (const float*)d_in[ix++];
    const float* h0      = (const float*)d_in[ix++];
    const float* c0      = (const float*)d_in[ix++];
    const float* context = (const float*)d_in[ix++];
    const int*   cur_lab = (const int*)  d_in[ix++];
    const int*   labels  = (const int*)  d_in[ix++];
    const float* emb     = (const float*)d_in[ix++];
    const float* W_ih    = (const float*)d_in[ix++];
    const float* b_ih    = (const float*)d_in[ix++];
    const float* W_hh    = (const float*)d_in[ix++];
    const float* b_hh    = (const float*)d_in[ix++];
    const float* W_ho    = (const float*)d_in[ix++];
    const float* b_ho    = (const float*)d_in[ix++];
    const float* W_ain   = (const float*)d_in[ix++];
    const float* b_ain   = (const float*)d_in[ix++];
    const float* W_actx  = (const float*)d_in[ix++];
    const float* b_actx  = (const float*)d_in[ix++];
    const float* Vv      = (const float*)d_in[ix++];
    const float* W_out   = (const float*)d_in[ix++];
    const float* b_out   = (const float*)d_in[ix++];

    float* out     = (float*)d_out;
    float* outputs = out;                               // B*T*NLAB
    float* preds   = out + (size_t)Bb * Tt * NLAB;      // B*T
    float* hf      = preds + (size_t)Bb * Tt;           // B*HID
    float* cf      = hf + (size_t)Bb * HID;             // B*HID

    float *ctx_proj, *tpb, *gates_x, *xcat, *cat3all, *gates, *hA, *hB, *cst, *hlstm, *qb;
    cudaGetSymbolAddress((void**)&ctx_proj, g_ctx_proj);
    cudaGetSymbolAddress((void**)&tpb,      g_tp);
    cudaGetSymbolAddress((void**)&gates_x,  g_gates_x);
    cudaGetSymbolAddress((void**)&xcat,     g_xcat);
    cudaGetSymbolAddress((void**)&cat3all,  g_cat3all);
    cudaGetSymbolAddress((void**)&gates,    g_gates);
    cudaGetSymbolAddress((void**)&hA,       g_hA);
    cudaGetSymbolAddress((void**)&hB,       g_hB);
    cudaGetSymbolAddress((void**)&cst,      g_cst);
    cudaGetSymbolAddress((void**)&hlstm,    g_hlstm);
    cudaGetSymbolAddress((void**)&qb,       g_q);

    // init recurrent state
    cudaMemcpyAsync(hA,  h0, (size_t)Bb * HID * sizeof(float), cudaMemcpyDeviceToDevice, 0);
    cudaMemcpyAsync(cst, c0, (size_t)Bb * HID * sizeof(float), cudaMemcpyDeviceToDevice, 0);

    // teacher-forced inputs
    build_xcat<<<(Bb * Tt * 2 * EMB + 255) / 256, 256>>>(dec_in, emb, cur_lab, labels, xcat);
    xcat_to_cat3<<<(Bb * Tt * EMB + 255) / 256, 256>>>(xcat, cat3all);

    // gates_x = xcat @ W_ih + b_ih   [12288 x 4096], K=512
    gemm64<<<dim3(G4H / 64, (Bb * Tt) / 64), 256>>>(
        xcat, 2 * EMB, nullptr, 0, 0, W_ih, G4H, b_ih, nullptr, 0,
        gates_x, G4H, nullptr, 0, 2 * EMB, 0);
    // ctx_proj = context @ W_actx + b_actx   [65536 x 1024], K=1024
    gemm64<<<dim3(HID / 64, (Bb * Ss) / 64), 256>>>(
        context, HID, nullptr, 0, 0, W_actx, HID, b_actx, nullptr, 0,
        ctx_proj, HID, nullptr, 0, HID, 0);
    // TP = tanh(ctx_proj), once
    tanh_ew<<<(Bb * Ss * HID + 255) / 256, 256>>>(ctx_proj, tpb, Bb * Ss * HID);

    float* hbufs[2] = {hA, hB};
    for (int t = 0; t < Tt; t++) {
        float* hin  = hbufs[t & 1];
        float* hout = hbufs[(t + 1) & 1];

        // gates = hin @ W_hh + b_hh + gates_x[:,t,:]
        gemm64<<<dim3(G4H / 64, Bb / 64), 256>>>(
            hin, HID, nullptr, 0, 0, W_hh, G4H, b_hh,
            gates_x + (size_t)t * G4H, Tt * G4H,
            gates, G4H, nullptr, 0, HID, 0);
        lstm_pw<<<(Bb * HID) / 256, 256>>>(gates, cst, hlstm);

        // tq = tanh(hlstm @ W_ain + b_ain)   (tanh epilogue — raw q never needed)
        gemm64<<<dim3(HID / 64, Bb / 64), 256>>>(
            hlstm, HID, nullptr, 0, 0, W_ain, HID, b_ain, nullptr, 0,
            qb, HID, nullptr, 0, HID, 1);

        // attention -> writes weighted into cat3all[., HID:2*HID]
        attn_k<<<Bb, 512>>>(qb, tpb, ctx_proj, Vv, cat3all, t);

        // hidden = tanh([weighted | hlstm] @ W_ho + b_ho); dup-store into cat3all[., 0:HID]
        gemm64<<<dim3(HID / 64, Bb / 64), 256>>>(
            cat3all + (size_t)t * CAT3 + HID, Tt * CAT3,   // A  = weighted rows (k<1024)
            hlstm, HID, HID,                               // A2 = hlstm (k>=1024)
            W_ho, HID, b_ho, nullptr, 0,
            hout, HID,
            cat3all + (size_t)t * CAT3, Tt * CAT3,         // C2 = hidden slot
            2 * HID, 1);
    }

    // deferred output projection: outputs = cat3all @ W_out + b_out  [12288 x 128], K=2304
    gemm64<<<dim3(NLAB / 64, (Bb * Tt) / 64), 256>>>(
        cat3all, CAT3, nullptr, 0, 0, W_out, NLAB, b_out, nullptr, 0,
        outputs, NLAB, nullptr, 0, CAT3, 0);

    // final states: carried hidden is post-attention hidden_t; after t=47 it sits in hbufs[0]
    cudaMemcpyAsync(hf, hbufs[Tt & 1], (size_t)Bb * HID * sizeof(float), cudaMemcpyDeviceToDevice, 0);
    cudaMemcpyAsync(cf, cst,           (size_t)Bb * HID * sizeof(float), cudaMemcpyDeviceToDevice, 0);

    // preds
    argmax_k<<<(Bb * Tt) / 8, 256>>>(outputs, preds);
}